// round 4
// baseline (speedup 1.0000x reference)
#include <cuda_runtime.h>

#define NE_MAX 500000
#define NRELS 256
#define DIM 256
#define SC_EPT 4          // edges per thread in scatter (1024 per block)
#define RCHUNK 1024       // edges per block in reduce

// ---- scratch (device globals; no allocation allowed) ----
__device__ int   g_counts[NRELS];
__device__ int   g_cursor[NRELS];
__device__ float g_inv[NRELS];
__device__ int   g_bsrc[NE_MAX];
__device__ int   g_bdst[NE_MAX];
__device__ int   g_brel[NE_MAX];
__device__ float g_Asum[2 * NRELS * DIM];   // rows 0-255 src sums, 256-511 dst sums
__device__ float g_H[2 * NRELS * DIM];      // rows 0-255 h_src, 256-511 h_dst
// G: [1024][768]; rows 0-511 = gi (avg @ W_ih^T), rows 512-1023 = gh (h @ W_hh^T)
__device__ float g_G[1024 * 768];

// ---------------- phase 0: zero counts + partial sums, unpack h ----------------
__global__ void init_kernel(const float* __restrict__ dyn) {
    int id = blockIdx.x * blockDim.x + threadIdx.x;   // 131072 threads
    if (id < NRELS) g_counts[id] = 0;
    if (id < 2 * NRELS * DIM / 4)
        ((float4*)g_Asum)[id] = make_float4(0.f, 0.f, 0.f, 0.f);
    // unpack dyn [r][0][d][k] -> g_H rows (k*256 + r)
    int r = id >> 9;            // 0..255
    int rem = id & 511;
    int d = rem >> 1;           // 0..255
    int k = rem & 1;
    g_H[(k * NRELS + r) * DIM + d] = dyn[r * (DIM * 2) + d * 2 + k];
}

// ---------------- phase 1: histogram of rel ----------------
__global__ void hist_kernel(const int* __restrict__ rel, int n) {
    __shared__ int h[NRELS];
    h[threadIdx.x] = 0;
    __syncthreads();
    for (int i = blockIdx.x * blockDim.x + threadIdx.x; i < n;
         i += gridDim.x * blockDim.x)
        atomicAdd(&h[rel[i]], 1);
    __syncthreads();
    int v = h[threadIdx.x];
    if (v) atomicAdd(&g_counts[threadIdx.x], v);
}

// ---------------- phase 2: exclusive scan + inverse counts ----------------
__global__ void scan_kernel() {
    __shared__ int s[NRELS];
    int t = threadIdx.x;
    int my = g_counts[t];
    s[t] = my;
    __syncthreads();
    for (int off = 1; off < NRELS; off <<= 1) {
        int v = (t >= off) ? s[t - off] : 0;
        __syncthreads();
        s[t] += v;
        __syncthreads();
    }
    g_cursor[t] = s[t] - my;   // exclusive prefix
    g_inv[t] = 1.f / (float)(my > 0 ? my : 1);
}

// ---------------- phase 3: scatter (block-local counting sort) ----------------
__global__ void __launch_bounds__(256) scatter_kernel(const int* __restrict__ src,
                                                      const int* __restrict__ dst,
                                                      const int* __restrict__ rel, int n) {
    __shared__ int lh[NRELS];
    __shared__ int base[NRELS];
    int t = threadIdx.x;
    lh[t] = 0;
    __syncthreads();

    int beg = blockIdx.x * (256 * SC_EPT);
    int s[SC_EPT], d[SC_EPT], r[SC_EPT];
#pragma unroll
    for (int j = 0; j < SC_EPT; j++) {
        int i = beg + j * 256 + t;       // coalesced
        if (i < n) {
            s[j] = src[i]; d[j] = dst[i]; r[j] = rel[i];
            atomicAdd(&lh[r[j]], 1);
        } else {
            r[j] = -1;
        }
    }
    __syncthreads();
    int c = lh[t];
    if (c) base[t] = atomicAdd(&g_cursor[t], c);
    __syncthreads();
    lh[t] = 0;
    __syncthreads();
#pragma unroll
    for (int j = 0; j < SC_EPT; j++) {
        if (r[j] >= 0) {
            int p = base[r[j]] + atomicAdd(&lh[r[j]], 1);
            g_bsrc[p] = s[j];
            g_bdst[p] = d[j];
            g_brel[p] = r[j];
        }
    }
}

// ---------------- phase 4: chunked segment-sum over sorted edges ----------------
__device__ __forceinline__ void flush_accum(int rel_id, int q,
                                            const float4& as, const float4& ad) {
    float* ps = &g_Asum[rel_id * DIM + q];
    float* pd = &g_Asum[(NRELS + rel_id) * DIM + q];
    atomicAdd(ps + 0, as.x); atomicAdd(ps + 1, as.y);
    atomicAdd(ps + 2, as.z); atomicAdd(ps + 3, as.w);
    atomicAdd(pd + 0, ad.x); atomicAdd(pd + 1, ad.y);
    atomicAdd(pd + 2, ad.z); atomicAdd(pd + 3, ad.w);
}

__global__ void __launch_bounds__(256) reduce_kernel(const float* __restrict__ emb, int n) {
    int beg = blockIdx.x * RCHUNK;
    int end = min(n, beg + RCHUNK);
    int t = threadIdx.x;
    int sub = t >> 6;            // 4 edges in flight per block
    int q   = (t & 63) << 2;     // float4 column

    float4 as = make_float4(0.f, 0.f, 0.f, 0.f);
    float4 ad = as;
    int cur = -1;

    int i = beg + sub;
    if (i < end) {
        int r = __ldcs(&g_brel[i]);   // read-once: evict-first, keep L2 for emb
        int s = __ldcs(&g_bsrc[i]);
        int d = __ldcs(&g_bdst[i]);
        while (true) {
            int inext = i + 4;
            bool more = inext < end;
            int rn = 0, sn = 0, dn = 0;
            if (more) {
                rn = __ldcs(&g_brel[inext]);
                sn = __ldcs(&g_bsrc[inext]);
                dn = __ldcs(&g_bdst[inext]);
            }
            float4 sv = __ldg((const float4*)&emb[s * DIM + q]);
            float4 dv = __ldg((const float4*)&emb[d * DIM + q]);
            if (r != cur) {
                if (cur >= 0) flush_accum(cur, q, as, ad);
                as = make_float4(0.f, 0.f, 0.f, 0.f);
                ad = as;
                cur = r;
            }
            as.x += sv.x; as.y += sv.y; as.z += sv.z; as.w += sv.w;
            ad.x += dv.x; ad.y += dv.y; ad.z += dv.z; ad.w += dv.w;
            if (!more) break;
            i = inext; r = rn; s = sn; d = dn;
        }
        flush_accum(cur, q, as, ad);
    }
}

// ---------------- phase 5: GEMM  G = [Asum*inv ; H] @ Wsel^T ----------------
// M = 1024 (rows 0-511: scaled Asum w/ W_ih; rows 512-1023: H w/ W_hh)
// Tile: TM=64 (M), TN=32 (N), TK=16. Grid (24, 16) = 384 blocks.
#define TM 64
#define TN 32
#define TK 16
__global__ void __launch_bounds__(256) gemm_kernel(const float* __restrict__ Wih,
                                                   const float* __restrict__ Whh) {
    __shared__ float As[TK][TM + 4];
    __shared__ float Bs[TK][TN + 4];
    int bm = blockIdx.y, bn = blockIdx.x;
    bool is_x = (bm < 8);
    const float* Wsel = is_x ? Wih : Whh;
    const float* Msrc = is_x ? g_Asum : g_H;
    int mbase = (is_x ? bm : bm - 8) * TM;   // row within 512-row half

    int tid = threadIdx.x;
    int tx = tid & 15;        // 16 n-subtiles * 2 = 32
    int ty = tid >> 4;        // 16 m-subtiles * 4 = 64
    int lrow  = tid >> 2;     // 0..63
    int lcol4 = (tid & 3) * 4;

    // per-A-row scale: rows of Asum scaled by g_inv[rel]; H rows scale 1
    int arow = mbase + lrow;                 // 0..511 within half
    float ascale = is_x ? g_inv[arow & 255] : 1.f;

    const float* Aptr = Msrc + arow * 256 + lcol4;
    const float* Bptr = Wsel + (bn * TN + (lrow & 31)) * 256 + lcol4 + ((lrow >> 5) ? 128 : 0);
    // threads with lrow<32 load B cols [lcol4, lcol4+4) ; lrow>=32 load cols +128
    // covers K halves: each k0 tile needs 32 rows x 16 cols -> 128 float4; we have
    // 256 loaders so split: loader group 0 handles k-offset 0 slice, group 1 handles +? 
    // Simpler correctness: see loop below (group1 disabled when redundant).

    float c[4][2] = {};

    for (int k0 = 0; k0 < 256; k0 += TK) {
        // A tile: 64 rows x 16 cols = 256 float4 -> all 256 threads
        float4 a4 = *(const float4*)(Aptr + k0);
        As[lcol4 + 0][lrow] = a4.x * ascale;
        As[lcol4 + 1][lrow] = a4.y * ascale;
        As[lcol4 + 2][lrow] = a4.z * ascale;
        As[lcol4 + 3][lrow] = a4.w * ascale;
        // B tile: 32 rows x 16 cols = 128 float4 -> threads with lrow < 32
        if (lrow < 32) {
            float4 b4 = *(const float4*)(Wsel + (bn * TN + lrow) * 256 + k0 + lcol4);
            Bs[lcol4 + 0][lrow] = b4.x;
            Bs[lcol4 + 1][lrow] = b4.y;
            Bs[lcol4 + 2][lrow] = b4.z;
            Bs[lcol4 + 3][lrow] = b4.w;
        }
        __syncthreads();
#pragma unroll
        for (int kk = 0; kk < TK; kk++) {
            float4 av = *(const float4*)&As[kk][ty * 4];
            float2 bv = *(const float2*)&Bs[kk][tx * 2];
            c[0][0] += av.x * bv.x; c[0][1] += av.x * bv.y;
            c[1][0] += av.y * bv.x; c[1][1] += av.y * bv.y;
            c[2][0] += av.z * bv.x; c[2][1] += av.z * bv.y;
            c[3][0] += av.w * bv.x; c[3][1] += av.w * bv.y;
        }
        __syncthreads();
    }

#pragma unroll
    for (int i = 0; i < 4; i++) {
        int row = bm * TM + ty * 4 + i;
        int col = bn * TN + tx * 2;
        *(float2*)&g_G[row * 768 + col] = make_float2(c[i][0], c[i][1]);
    }
}

// ---------------- phase 6: GRU gates + output ----------------
__global__ void gate_kernel(const float* __restrict__ bih,
                            const float* __restrict__ bhh,
                            float* __restrict__ out) {
    int r = blockIdx.x;
    int d = threadIdx.x;

    float bir = bih[d], biz = bih[256 + d], bin_ = bih[512 + d];
    float bhr = bhh[d], bhz = bhh[256 + d], bhn = bhh[512 + d];

#pragma unroll
    for (int k = 0; k < 2; k++) {   // 0 = src, 1 = dst
        int xrow = k * 256 + r;       // gi rows 0-511
        int hrow = 512 + k * 256 + r; // gh rows 512-1023
        float ir  = g_G[xrow * 768 + d]       + bir;
        float iz  = g_G[xrow * 768 + 256 + d] + biz;
        float in_ = g_G[xrow * 768 + 512 + d] + bin_;
        float hr  = g_G[hrow * 768 + d]       + bhr;
        float hz  = g_G[hrow * 768 + 256 + d] + bhz;
        float hn  = g_G[hrow * 768 + 512 + d] + bhn;
        float h   = g_H[(k * NRELS + r) * DIM + d];

        float rg = 1.f / (1.f + expf(-(ir + hr)));
        float z  = 1.f / (1.f + expf(-(iz + hz)));
        float nv = tanhf(in_ + rg * hn);
        out[r * (DIM * 2) + d * 2 + k] = (1.f - z) * nv + z * h;
    }
}

extern "C" void kernel_launch(void* const* d_in, const int* in_sizes, int n_in,
                              void* d_out, int out_size) {
    const int*   src = (const int*)d_in[0];
    const int*   dst = (const int*)d_in[1];
    const int*   rel = (const int*)d_in[2];
    const float* emb = (const float*)d_in[3];
    const float* dyn = (const float*)d_in[4];
    const float* Wih = (const float*)d_in[5];
    const float* Whh = (const float*)d_in[6];
    const float* bih = (const float*)d_in[7];
    const float* bhh = (const float*)d_in[8];
    float* out = (float*)d_out;
    int n = in_sizes[0];

    init_kernel<<<512, 256>>>(dyn);
    hist_kernel<<<512, 256>>>(rel, n);
    scan_kernel<<<1, 256>>>();
    int nbS = (n + 256 * SC_EPT - 1) / (256 * SC_EPT);
    scatter_kernel<<<nbS, 256>>>(src, dst, rel, n);
    int nbR = (n + RCHUNK - 1) / RCHUNK;
    reduce_kernel<<<nbR, 256>>>(emb, n);
    gemm_kernel<<<dim3(24, 16), 256>>>(Wih, Whh);
    gate_kernel<<<256, 256>>>(bih, bhh, out);
}

// round 5
// speedup vs baseline: 1.1793x; 1.1793x over previous
#include <cuda_runtime.h>

#define NE_MAX 500000
#define NRELS 256
#define DIM 256
#define SC_EPT 8          // edges per thread in scatter (2048 per block)
#define RCHUNK 512        // edges per block in reduce (977 blocks)

// ---- scratch (device globals; no allocation allowed) ----
__device__ int   g_counts[NRELS];
__device__ int   g_cursor[NRELS];
__device__ int   g_bsrc[NE_MAX];
__device__ int   g_bdst[NE_MAX];
__device__ int   g_brel[NE_MAX];
__device__ float g_Asum[2 * NRELS * DIM];   // rows 0-255 src sums, 256-511 dst sums
// A: rows 0-255 src_avg, 256-511 dst_avg, 512-767 h_src, 768-1023 h_dst
__device__ float g_A[1024 * DIM];
// G: [1024][768] = A @ Wsel^T  (rows <512 use W_ih, rows >=512 use W_hh)
__device__ float g_G[1024 * 768];

// ---------------- phase 0: zero counts + partial-sum buffer ----------------
__global__ void init_kernel() {
    int id = blockIdx.x * blockDim.x + threadIdx.x;   // 32768
    if (id < NRELS) g_counts[id] = 0;
    float4 z = make_float4(0.f, 0.f, 0.f, 0.f);
    ((float4*)g_Asum)[id] = z;                        // 32768 float4 = 131072 floats
}

// ---------------- phase 1: histogram of rel ----------------
__global__ void hist_kernel(const int* __restrict__ rel, int n) {
    __shared__ int h[NRELS];
    h[threadIdx.x] = 0;
    __syncthreads();
    for (int i = blockIdx.x * blockDim.x + threadIdx.x; i < n;
         i += gridDim.x * blockDim.x)
        atomicAdd(&h[rel[i]], 1);
    __syncthreads();
    int v = h[threadIdx.x];
    if (v) atomicAdd(&g_counts[threadIdx.x], v);
}

// ---------------- phase 2: exclusive scan (256 bins, 1 block) ----------------
__global__ void scan_kernel() {
    __shared__ int s[NRELS];
    int t = threadIdx.x;
    int my = g_counts[t];
    s[t] = my;
    __syncthreads();
    for (int off = 1; off < NRELS; off <<= 1) {
        int v = (t >= off) ? s[t - off] : 0;
        __syncthreads();
        s[t] += v;
        __syncthreads();
    }
    g_cursor[t] = s[t] - my;   // exclusive prefix
}

// ---------------- phase 3: scatter (block-local counting sort) ----------------
__global__ void __launch_bounds__(256) scatter_kernel(const int* __restrict__ src,
                                                      const int* __restrict__ dst,
                                                      const int* __restrict__ rel, int n) {
    __shared__ int lh[NRELS];
    __shared__ int base[NRELS];
    int t = threadIdx.x;
    lh[t] = 0;
    __syncthreads();

    int beg = blockIdx.x * (256 * SC_EPT);
    int s[SC_EPT], d[SC_EPT], r[SC_EPT];
#pragma unroll
    for (int j = 0; j < SC_EPT; j++) {
        int i = beg + j * 256 + t;       // coalesced
        if (i < n) {
            s[j] = src[i]; d[j] = dst[i]; r[j] = rel[i];
            atomicAdd(&lh[r[j]], 1);
        } else {
            r[j] = -1;
        }
    }
    __syncthreads();
    int c = lh[t];
    if (c) base[t] = atomicAdd(&g_cursor[t], c);   // one global atomic per (block,bin)
    __syncthreads();
    lh[t] = 0;
    __syncthreads();
#pragma unroll
    for (int j = 0; j < SC_EPT; j++) {
        if (r[j] >= 0) {
            int p = base[r[j]] + atomicAdd(&lh[r[j]], 1);
            g_bsrc[p] = s[j];
            g_bdst[p] = d[j];
            g_brel[p] = r[j];
        }
    }
}

// ---------------- copy hidden state rows into A ----------------
__global__ void copy_h_kernel(const float* __restrict__ dyn) {
    int id = blockIdx.x * blockDim.x + threadIdx.x;  // 65536
    int r = id >> 8, d = id & 255;
    g_A[(512 + r) * DIM + d] = dyn[r * (DIM * 2) + d * 2 + 0];
    g_A[(768 + r) * DIM + d] = dyn[r * (DIM * 2) + d * 2 + 1];
}

// ---------------- phase 4: chunked segment-sum over sorted edges ----------------
__device__ __forceinline__ void flush_accum(int rel_id, int q,
                                            const float4& as, const float4& ad) {
    float* ps = &g_Asum[rel_id * DIM + q];
    float* pd = &g_Asum[(NRELS + rel_id) * DIM + q];
    atomicAdd(ps + 0, as.x); atomicAdd(ps + 1, as.y);
    atomicAdd(ps + 2, as.z); atomicAdd(ps + 3, as.w);
    atomicAdd(pd + 0, ad.x); atomicAdd(pd + 1, ad.y);
    atomicAdd(pd + 2, ad.z); atomicAdd(pd + 3, ad.w);
}

__global__ void __launch_bounds__(256) reduce_kernel(const float* __restrict__ emb, int n) {
    int beg = blockIdx.x * RCHUNK;
    int end = min(n, beg + RCHUNK);
    int t = threadIdx.x;
    int sub = t >> 6;            // 4 edge streams per block, stride 4
    int q   = (t & 63) << 2;     // float4 column

    float4 as = make_float4(0.f, 0.f, 0.f, 0.f);
    float4 ad = as;
    int cur = -1;

    int i = beg + sub;
    // main loop: 2 edges per iteration -> 4 independent float4 gathers in flight
    for (; i + 4 < end; i += 8) {
        int r0 = __ldg(&g_brel[i]);
        int s0 = __ldg(&g_bsrc[i]);
        int d0 = __ldg(&g_bdst[i]);
        int r1 = __ldg(&g_brel[i + 4]);
        int s1 = __ldg(&g_bsrc[i + 4]);
        int d1 = __ldg(&g_bdst[i + 4]);
        float4 sv0 = __ldg((const float4*)&emb[s0 * DIM + q]);
        float4 dv0 = __ldg((const float4*)&emb[d0 * DIM + q]);
        float4 sv1 = __ldg((const float4*)&emb[s1 * DIM + q]);
        float4 dv1 = __ldg((const float4*)&emb[d1 * DIM + q]);
        if (r0 != cur) {
            if (cur >= 0) flush_accum(cur, q, as, ad);
            as = make_float4(0.f, 0.f, 0.f, 0.f); ad = as;
            cur = r0;
        }
        as.x += sv0.x; as.y += sv0.y; as.z += sv0.z; as.w += sv0.w;
        ad.x += dv0.x; ad.y += dv0.y; ad.z += dv0.z; ad.w += dv0.w;
        if (r1 != cur) {
            flush_accum(cur, q, as, ad);
            as = make_float4(0.f, 0.f, 0.f, 0.f); ad = as;
            cur = r1;
        }
        as.x += sv1.x; as.y += sv1.y; as.z += sv1.z; as.w += sv1.w;
        ad.x += dv1.x; ad.y += dv1.y; ad.z += dv1.z; ad.w += dv1.w;
    }
    // tail: at most one edge left in this stream
    for (; i < end; i += 4) {
        int r = __ldg(&g_brel[i]);
        int s = __ldg(&g_bsrc[i]);
        int d = __ldg(&g_bdst[i]);
        float4 sv = __ldg((const float4*)&emb[s * DIM + q]);
        float4 dv = __ldg((const float4*)&emb[d * DIM + q]);
        if (r != cur) {
            if (cur >= 0) flush_accum(cur, q, as, ad);
            as = make_float4(0.f, 0.f, 0.f, 0.f); ad = as;
            cur = r;
        }
        as.x += sv.x; as.y += sv.y; as.z += sv.z; as.w += sv.w;
        ad.x += dv.x; ad.y += dv.y; ad.z += dv.z; ad.w += dv.w;
    }
    if (cur >= 0) flush_accum(cur, q, as, ad);
}

// ---------------- phase 4b: divide by counts ----------------
__global__ void finalize_kernel() {
    int r = blockIdx.x, t = threadIdx.x;
    int c = g_counts[r];
    float inv = 1.f / (float)(c > 0 ? c : 1);
    g_A[r * DIM + t]           = g_Asum[r * DIM + t] * inv;
    g_A[(NRELS + r) * DIM + t] = g_Asum[(NRELS + r) * DIM + t] * inv;
}

// ---------------- phase 5: GEMM  G[1024][768] = A[1024][256] @ Wsel[768][256]^T
#define TM 64
#define TN 64
#define TK 16
__global__ void __launch_bounds__(256) gemm_kernel(const float* __restrict__ Wih,
                                                   const float* __restrict__ Whh) {
    __shared__ float As[TK][TM + 4];
    __shared__ float Bs[TK][TN + 4];
    int bm = blockIdx.y, bn = blockIdx.x;
    const float* Wsel = (bm < 8) ? Wih : Whh;

    int tid = threadIdx.x;
    int tx = tid & 15;
    int ty = tid >> 4;
    int lrow  = tid >> 2;
    int lcol4 = (tid & 3) * 4;

    const float* Aptr = g_A  + (bm * TM + lrow) * 256 + lcol4;
    const float* Bptr = Wsel + (bn * TN + lrow) * 256 + lcol4;

    float c[4][4] = {};

    for (int k0 = 0; k0 < 256; k0 += TK) {
        float4 a4 = *(const float4*)(Aptr + k0);
        float4 b4 = *(const float4*)(Bptr + k0);
        As[lcol4 + 0][lrow] = a4.x;
        As[lcol4 + 1][lrow] = a4.y;
        As[lcol4 + 2][lrow] = a4.z;
        As[lcol4 + 3][lrow] = a4.w;
        Bs[lcol4 + 0][lrow] = b4.x;
        Bs[lcol4 + 1][lrow] = b4.y;
        Bs[lcol4 + 2][lrow] = b4.z;
        Bs[lcol4 + 3][lrow] = b4.w;
        __syncthreads();
#pragma unroll
        for (int kk = 0; kk < TK; kk++) {
            float4 av = *(const float4*)&As[kk][ty * 4];
            float4 bv = *(const float4*)&Bs[kk][tx * 4];
            c[0][0] += av.x * bv.x; c[0][1] += av.x * bv.y; c[0][2] += av.x * bv.z; c[0][3] += av.x * bv.w;
            c[1][0] += av.y * bv.x; c[1][1] += av.y * bv.y; c[1][2] += av.y * bv.z; c[1][3] += av.y * bv.w;
            c[2][0] += av.z * bv.x; c[2][1] += av.z * bv.y; c[2][2] += av.z * bv.z; c[2][3] += av.z * bv.w;
            c[3][0] += av.w * bv.x; c[3][1] += av.w * bv.y; c[3][2] += av.w * bv.z; c[3][3] += av.w * bv.w;
        }
        __syncthreads();
    }

#pragma unroll
    for (int i = 0; i < 4; i++) {
        int row = bm * TM + ty * 4 + i;
        int col = bn * TN + tx * 4;
        float4 v = make_float4(c[i][0], c[i][1], c[i][2], c[i][3]);
        *(float4*)&g_G[row * 768 + col] = v;
    }
}

// ---------------- phase 6: GRU gates + output ----------------
__global__ void gate_kernel(const float* __restrict__ bih,
                            const float* __restrict__ bhh,
                            float* __restrict__ out) {
    int r = blockIdx.x;
    int d = threadIdx.x;

    float bir = bih[d], biz = bih[256 + d], bin_ = bih[512 + d];
    float bhr = bhh[d], bhz = bhh[256 + d], bhn = bhh[512 + d];

#pragma unroll
    for (int k = 0; k < 2; k++) {   // 0 = src, 1 = dst
        int xrow = k * 256 + r;
        int hrow = 512 + k * 256 + r;
        float ir  = g_G[xrow * 768 + d]       + bir;
        float iz  = g_G[xrow * 768 + 256 + d] + biz;
        float in_ = g_G[xrow * 768 + 512 + d] + bin_;
        float hr  = g_G[hrow * 768 + d]       + bhr;
        float hz  = g_G[hrow * 768 + 256 + d] + bhz;
        float hn  = g_G[hrow * 768 + 512 + d] + bhn;
        float h   = g_A[hrow * DIM + d];

        float rg = 1.f / (1.f + expf(-(ir + hr)));
        float z  = 1.f / (1.f + expf(-(iz + hz)));
        float nv = tanhf(in_ + rg * hn);
        out[r * (DIM * 2) + d * 2 + k] = (1.f - z) * nv + z * h;
    }
}

extern "C" void kernel_launch(void* const* d_in, const int* in_sizes, int n_in,
                              void* d_out, int out_size) {
    const int*   src = (const int*)d_in[0];
    const int*   dst = (const int*)d_in[1];
    const int*   rel = (const int*)d_in[2];
    const float* emb = (const float*)d_in[3];
    const float* dyn = (const float*)d_in[4];
    const float* Wih = (const float*)d_in[5];
    const float* Whh = (const float*)d_in[6];
    const float* bih = (const float*)d_in[7];
    const float* bhh = (const float*)d_in[8];
    float* out = (float*)d_out;
    int n = in_sizes[0];

    init_kernel<<<128, 256>>>();
    hist_kernel<<<512, 256>>>(rel, n);
    scan_kernel<<<1, 256>>>();
    int nbS = (n + 256 * SC_EPT - 1) / (256 * SC_EPT);
    scatter_kernel<<<nbS, 256>>>(src, dst, rel, n);
    copy_h_kernel<<<256, 256>>>(dyn);
    int nbR = (n + RCHUNK - 1) / RCHUNK;
    reduce_kernel<<<nbR, 256>>>(emb, n);
    finalize_kernel<<<256, 256>>>();
    gemm_kernel<<<dim3(12, 16), 256>>>(Wih, Whh);
    gate_kernel<<<256, 256>>>(bih, bhh, out);
}